// round 4
// baseline (speedup 1.0000x reference)
#include <cuda_runtime.h>
#include <cstdint>

#define NB 16
#define KG 50
#define HH 64
#define WW 64
#define NA 9
#define NN (HH*WW*NA)      // 36864
#define HW (HH*WW)         // 4096
#define SEL_CAP 2048
#define SEL_T 512

// base anchors (ratios 0.5/1/2 x scales 8/16/32), exact fp32 values
__constant__ float c_base[NA][4] = {
  { -84.f,  -40.f,  99.f,  55.f},
  {-176.f,  -88.f, 191.f, 103.f},
  {-360.f, -184.f, 375.f, 199.f},
  { -56.f,  -56.f,  71.f,  71.f},
  {-120.f, -120.f, 135.f, 135.f},
  {-248.f, -248.f, 263.f, 263.f},
  { -36.f,  -80.f,  51.f,  95.f},
  { -80.f, -168.f,  95.f, 183.f},
  {-168.f, -344.f, 183.f, 359.f}
};

// arrays indexed [b][a*HW+hw] for coalescing; candidate packs use reference idx i = hw*NA+a
__device__ float              g_gtmax[NB][KG];
__device__ unsigned char      g_lab[NB][NN];   // 0:-1  1:bg  2:fg  3:outside
__device__ unsigned short     g_arg[NB][NN];
__device__ unsigned int       g_r[NB][NN];
__device__ int                g_cnt[NB][2];
__device__ unsigned long long g_cand[NB][2][NN];  // (r<<32)|ref_i
__device__ uint2              g_thr[NB][2];    // keep iff r>thr.x || (r==thr.x && i<=thr.y)
__device__ float              g_uw[NB];

struct Keys { unsigned int kf[NB][2]; unsigned int kb[NB][2]; };

__host__ __device__ __forceinline__ unsigned int rotl32(unsigned int x, int r) {
  return (x << r) | (x >> (32 - r));
}

__host__ __device__ __forceinline__ void tf2x32(unsigned int k0, unsigned int k1,
                                                unsigned int x0, unsigned int x1,
                                                unsigned int &o0, unsigned int &o1) {
  unsigned int ks2 = k0 ^ k1 ^ 0x1BD11BDAu;
  x0 += k0; x1 += k1;
  const int ra[4] = {13, 15, 26, 6};
  const int rb[4] = {17, 29, 16, 24};
  #pragma unroll
  for (int j = 0; j < 4; j++) { x0 += x1; x1 = rotl32(x1, ra[j]); x1 ^= x0; }
  x0 += k1;  x1 += ks2 + 1u;
  #pragma unroll
  for (int j = 0; j < 4; j++) { x0 += x1; x1 = rotl32(x1, rb[j]); x1 ^= x0; }
  x0 += ks2; x1 += k0 + 2u;
  #pragma unroll
  for (int j = 0; j < 4; j++) { x0 += x1; x1 = rotl32(x1, ra[j]); x1 ^= x0; }
  x0 += k0;  x1 += k1 + 3u;
  #pragma unroll
  for (int j = 0; j < 4; j++) { x0 += x1; x1 = rotl32(x1, rb[j]); x1 ^= x0; }
  x0 += k1;  x1 += ks2 + 4u;
  #pragma unroll
  for (int j = 0; j < 4; j++) { x0 += x1; x1 = rotl32(x1, ra[j]); x1 ^= x0; }
  x0 += ks2; x1 += k0 + 5u;
  o0 = x0; o1 = x1;
}

__device__ __forceinline__ void load_gts4(const float* __restrict__ gt_boxes, int b, int t,
                                          float4* s_g, float* s_ga) {
  if (t < KG) {
    const float* g = gt_boxes + (b * KG + t) * 5;
    float g0 = g[0], g1 = g[1], g2 = g[2], g3 = g[3];
    s_g[t] = make_float4(g0, g1, g2, g3);
    s_ga[t] = __fmul_rn(__fadd_rn(__fsub_rn(g2, g0), 1.0f),
                        __fadd_rn(__fsub_rn(g3, g1), 1.0f));
  }
}

__global__ void k_init() {
  int idx = threadIdx.x;
  if (idx < NB * KG) ((float*)g_gtmax)[idx] = 0.0f;
  if (idx < NB * 2)  ((int*)g_cnt)[idx] = 0;
}

// grid (HW/256, NA, NB)
__global__ void k_gtmax(const float* __restrict__ gt_boxes, const float* __restrict__ im_info) {
  __shared__ float4 s_g[KG];
  __shared__ float s_ga[KG];
  __shared__ int s_max[KG];
  int b = blockIdx.z;
  int a = blockIdx.y;
  int t = threadIdx.x;
  load_gts4(gt_boxes, b, t, s_g, s_ga);
  if (t < KG) s_max[t] = 0;
  __syncthreads();
  int hw = blockIdx.x * blockDim.x + t;
  float img_h = im_info[0], img_w = im_info[1];
  int w = hw & 63; int h = hw >> 6;
  float sx = (float)(w * 16), sy = (float)(h * 16);
  float ax1 = c_base[a][0] + sx, ay1 = c_base[a][1] + sy;
  float ax2 = c_base[a][2] + sx, ay2 = c_base[a][3] + sy;
  bool inside = (ax1 >= 0.f) && (ay1 >= 0.f) && (ax2 < img_w) && (ay2 < img_h);
  if (inside) {
    float aw = __fadd_rn(__fsub_rn(ax2, ax1), 1.0f);
    float ah = __fadd_rn(__fsub_rn(ay2, ay1), 1.0f);
    float aarea = __fmul_rn(aw, ah);
    unsigned mask = __activemask();
    int lane = t & 31;
    int leader = __ffs(mask) - 1;
    #pragma unroll 5
    for (int k = 0; k < KG; k++) {
      float4 gk = s_g[k];
      float ix = __fadd_rn(__fsub_rn(fminf(ax2, gk.z), fmaxf(ax1, gk.x)), 1.0f);
      float iy = __fadd_rn(__fsub_rn(fminf(ay2, gk.w), fmaxf(ay1, gk.y)), 1.0f);
      int ovb = 0;
      if (fminf(ix, iy) > 0.f) {
        float inter = __fmul_rn(ix, iy);
        float denom = __fsub_rn(__fadd_rn(aarea, s_ga[k]), inter);
        ovb = __float_as_int(__fdiv_rn(inter, denom));
      }
      int mv = __reduce_max_sync(mask, ovb);
      if (lane == leader && mv > 0) atomicMax(&s_max[k], mv);
    }
  }
  __syncthreads();
  if (t < KG) {
    int v = s_max[t];
    if (v > 0) atomicMax((int*)&g_gtmax[b][t], v);
  }
}

__global__ void k_label(const float* __restrict__ gt_boxes, const float* __restrict__ im_info,
                        Keys keys) {
  __shared__ float4 s_g[KG];
  __shared__ float s_ga[KG];
  __shared__ float s_gm[KG];
  int b = blockIdx.z;
  int a = blockIdx.y;
  int t = threadIdx.x;
  load_gts4(gt_boxes, b, t, s_g, s_ga);
  if (t < KG) {
    float gm = g_gtmax[b][t];
    s_gm[t] = (gm == 0.f) ? 1e-5f : gm;
  }
  __syncthreads();
  int hw = blockIdx.x * blockDim.x + t;
  int i = hw * NA + a;          // reference anchor index (for tie-breaks)
  int si = a * HW + hw;         // storage index (coalesced)
  float img_h = im_info[0], img_w = im_info[1];
  int w = hw & 63; int h = hw >> 6;
  float sx = (float)(w * 16), sy = (float)(h * 16);
  float ax1 = c_base[a][0] + sx, ay1 = c_base[a][1] + sy;
  float ax2 = c_base[a][2] + sx, ay2 = c_base[a][3] + sy;
  bool inside = (ax1 >= 0.f) && (ay1 >= 0.f) && (ax2 < img_w) && (ay2 < img_h);

  int type = -1;
  unsigned char code = 3;
  if (inside) {
    float aw = __fadd_rn(__fsub_rn(ax2, ax1), 1.0f);
    float ah = __fadd_rn(__fsub_rn(ay2, ay1), 1.0f);
    float aarea = __fmul_rn(aw, ah);
    float maxov = 0.0f; int arg = 0; bool best = false;
    #pragma unroll 5
    for (int k = 0; k < KG; k++) {
      float4 gk = s_g[k];
      float ix = __fadd_rn(__fsub_rn(fminf(ax2, gk.z), fmaxf(ax1, gk.x)), 1.0f);
      float iy = __fadd_rn(__fsub_rn(fminf(ay2, gk.w), fmaxf(ay1, gk.y)), 1.0f);
      if (fminf(ix, iy) > 0.f) {
        float inter = __fmul_rn(ix, iy);
        float denom = __fsub_rn(__fadd_rn(aarea, s_ga[k]), inter);
        float ov = __fdiv_rn(inter, denom);
        if (ov > maxov) { maxov = ov; arg = k; }
        if (ov == s_gm[k]) best = true;
      }
    }
    if (best || (maxov >= 0.7f)) code = 2;
    else if (maxov < 0.3f)       code = 1;
    else                         code = 0;
    g_arg[b][si] = (unsigned short)arg;
    if (code >= 1) type = (code == 2) ? 0 : 1;
  }
  g_lab[b][si] = code;

  unsigned int r = 0;
  if (type >= 0) {
    unsigned int k0 = (type == 0) ? keys.kf[b][0] : keys.kb[b][0];
    unsigned int k1 = (type == 0) ? keys.kf[b][1] : keys.kb[b][1];
    unsigned int o0, o1;
    tf2x32(k0, k1, 0u, (unsigned int)i, o0, o1);
    r = (o0 ^ o1) >> 9;
    g_r[b][si] = r;
  }
  // warp-aggregated candidate append
  unsigned mf = __ballot_sync(0xFFFFFFFFu, type == 0);
  unsigned mb = __ballot_sync(0xFFFFFFFFu, type == 1);
  int lane = t & 31;
  unsigned lt = (1u << lane) - 1u;
  unsigned long long pk = ((unsigned long long)r << 32) | (unsigned long long)(unsigned)i;
  if (type == 0) {
    int ldr = __ffs(mf) - 1;
    int pos;
    if (lane == ldr) pos = atomicAdd(&g_cnt[b][0], __popc(mf));
    pos = __shfl_sync(mf, pos, ldr);
    g_cand[b][0][pos + __popc(mf & lt)] = pk;
  } else if (type == 1) {
    int ldr = __ffs(mb) - 1;
    int pos;
    if (lane == ldr) pos = atomicAdd(&g_cnt[b][1], __popc(mb));
    pos = __shfl_sync(mb, pos, ldr);
    g_cand[b][1][pos + __popc(mb & lt)] = pk;
  }
}

// One block per (batch,type); 512 threads, MLP-4 batched scans of compact list.
__global__ void k_select() {
  __shared__ unsigned int sh[2048];
  __shared__ unsigned int ss[513];
  __shared__ unsigned long long lst[SEL_CAP];
  __shared__ int s_tb, s_K1, s_lc;

  int b = blockIdx.x >> 1;
  int type = blockIdx.x & 1;
  int t = threadIdx.x;

  int cnt = g_cnt[b][type];
  int cnt_fg = g_cnt[b][0];
  int kept_fg = min(cnt_fg, 128);
  int K = (type == 0) ? 128 : (256 - kept_fg);
  if (type == 1 && t == 0) {
    int kept_bg = min(cnt, K);
    g_uw[b] = __fdiv_rn(1.0f, (float)(kept_fg + kept_bg));
  }
  if (cnt <= K) {
    if (t == 0) g_thr[b][type] = make_uint2(0u, 0xFFFFFFFFu);
    return;
  }
  const unsigned long long* cand = g_cand[b][type];
  for (int j = t; j < 2048; j += SEL_T) sh[j] = 0u;
  if (t == 0) { ss[512] = 0u; s_lc = 0; }
  __syncthreads();
  // pass 1: histogram of r>>12, 4 loads in flight
  for (int base = t; base < cnt; base += SEL_T * 4) {
    unsigned long long v[4];
    #pragma unroll
    for (int j = 0; j < 4; j++) {
      int c = base + j * SEL_T;
      v[j] = (c < cnt) ? cand[c] : 0ull;
    }
    #pragma unroll
    for (int j = 0; j < 4; j++) {
      int c = base + j * SEL_T;
      if (c < cnt) atomicAdd(&sh[(unsigned int)(v[j] >> 32) >> 12], 1u);
    }
  }
  __syncthreads();
  unsigned int cs = 0;
  #pragma unroll
  for (int k = 0; k < 4; k++) cs += sh[t * 4 + k];
  ss[t] = cs;
  __syncthreads();
  #pragma unroll
  for (int off = 1; off < 512; off <<= 1) {
    unsigned int v = (t + off < 512) ? ss[t + off] : 0u;
    __syncthreads();
    ss[t] += v;
    __syncthreads();
  }
  {
    int run = (int)ss[t + 1];
    #pragma unroll
    for (int k = 3; k >= 0; k--) {
      int j = t * 4 + k;
      int hj = (int)sh[j];
      if (run < K && run + hj >= K) { s_tb = j; s_K1 = K - run; }
      run += hj;
    }
  }
  __syncthreads();
  int tb = s_tb;
  // pass 2: collect threshold-bin entries, 4 loads in flight
  for (int base = t; base < cnt; base += SEL_T * 4) {
    unsigned long long v[4];
    #pragma unroll
    for (int j = 0; j < 4; j++) {
      int c = base + j * SEL_T;
      v[j] = (c < cnt) ? cand[c] : 0ull;
    }
    #pragma unroll
    for (int j = 0; j < 4; j++) {
      int c = base + j * SEL_T;
      if (c < cnt) {
        unsigned int r = (unsigned int)(v[j] >> 32);
        if ((int)(r >> 12) == tb) {
          int p = atomicAdd(&s_lc, 1);
          if (p < SEL_CAP)
            lst[p] = ((unsigned long long)r << 32) |
                     (unsigned long long)(0xFFFFFFFFu - (unsigned int)(v[j] & 0xFFFFFFFFull));
        }
      }
    }
  }
  __syncthreads();
  if (t == 0) {
    int n = min(s_lc, SEL_CAP);
    for (int x = 1; x < n; x++) {
      unsigned long long v = lst[x]; int y = x - 1;
      while (y >= 0 && lst[y] < v) { lst[y + 1] = lst[y]; y--; }
      lst[y + 1] = v;
    }
    int k1 = s_K1; if (k1 > n) k1 = n;
    unsigned long long kk = lst[k1 - 1];
    g_thr[b][type] = make_uint2((unsigned int)(kk >> 32),
                                0xFFFFFFFFu - (unsigned int)(kk & 0xFFFFFFFFull));
  }
}

__global__ void k_out(const float* __restrict__ gt_boxes, float* __restrict__ out) {
  const int TBASE = NB * NN;
  const int IBASE = TBASE + NB * NN * 4;
  const int OBASE = IBASE + NB * NN * 4;
  __shared__ float4 s_gt[KG];
  int bid = blockIdx.x;
  int hblk = bid % (HH / 4);
  int tmp = bid / (HH / 4);
  int a = tmp % NA;
  int b = tmp / NA;
  if (threadIdx.x < KG) {
    const float* g = gt_boxes + (b * KG + threadIdx.x) * 5;
    s_gt[threadIdx.x] = make_float4(g[0], g[1], g[2], g[3]);
  }
  __syncthreads();
  int w = threadIdx.x & 63;
  int h = hblk * 4 + (threadIdx.x >> 6);
  int hw = h * WW + w;
  int i = hw * NA + a;          // reference index (tie-break)
  int si = a * HW + hw;         // storage index

  int base_l = b * NN + (a * HH + h) * WW + w;
  int off = b * (NN * 4) + hw;

  unsigned char code = g_lab[b][si];
  if (code == 3) {
    out[base_l] = 0.f;
    #pragma unroll
    for (int c = 0; c < 4; c++) {
      int o = off + (a * 4 + c) * HW;
      out[TBASE + o] = 0.f; out[IBASE + o] = 0.f; out[OBASE + o] = 0.f;
    }
    return;
  }
  float lblv; bool is_pos = false, counted = false;
  if (code == 0) lblv = -1.f;
  else {
    int type = (code == 2) ? 0 : 1;
    uint2 thr = g_thr[b][type];
    unsigned int r = g_r[b][si];
    bool keep = (r > thr.x) || ((r == thr.x) && ((unsigned int)i <= thr.y));
    if (code == 2) { lblv = keep ? 1.f : -1.f; is_pos = keep; counted = keep; }
    else           { lblv = keep ? 0.f : -1.f; counted = keep; }
  }
  out[base_l] = lblv;

  int arg = g_arg[b][si];
  float4 g = s_gt[arg];
  float sx = (float)(w * 16), sy = (float)(h * 16);
  float ax1 = c_base[a][0] + sx, ay1 = c_base[a][1] + sy;
  float ax2 = c_base[a][2] + sx, ay2 = c_base[a][3] + sy;
  float aw = ax2 - ax1 + 1.f, ah = ay2 - ay1 + 1.f;
  float acx = ax1 + 0.5f * (aw - 1.f), acy = ay1 + 0.5f * (ah - 1.f);
  float gw = g.z - g.x + 1.f, gh = g.w - g.y + 1.f;
  float gcx = g.x + 0.5f * (gw - 1.f), gcy = g.y + 0.5f * (gh - 1.f);
  float tx = __fdividef(gcx - acx, aw), ty = __fdividef(gcy - acy, ah);
  float tw = __logf(__fdividef(gw, aw)), th = __logf(__fdividef(gh, ah));

  float inw = is_pos ? 1.f : 0.f;
  float ow  = counted ? g_uw[b] : 0.f;
  float tgt[4] = {tx, ty, tw, th};
  #pragma unroll
  for (int c = 0; c < 4; c++) {
    int o = off + (a * 4 + c) * HW;
    out[TBASE + o] = tgt[c];
    out[IBASE + o] = inw;
    out[OBASE + o] = ow;
  }
}

extern "C" void kernel_launch(void* const* d_in, const int* in_sizes, int n_in,
                              void* d_out, int out_size) {
  const float* gt = (const float*)d_in[1];
  const float* iminfo = (const float*)d_in[2];
  float* out = (float*)d_out;

  Keys keys;
  for (int b = 0; b < NB; b++) {
    unsigned int a0, a1;
    tf2x32(0u, 42u, 0u, (unsigned int)b, a0, a1);
    tf2x32(a0, a1, 0u, 0u, keys.kf[b][0], keys.kf[b][1]);
    tf2x32(a0, a1, 0u, 1u, keys.kb[b][0], keys.kb[b][1]);
  }

  k_init<<<1, 1024>>>();
  dim3 g1(HW / 256, NA, NB);
  k_gtmax<<<g1, 256>>>(gt, iminfo);
  k_label<<<g1, 256>>>(gt, iminfo, keys);
  k_select<<<NB * 2, SEL_T>>>();
  k_out<<<NB * NA * (HH / 4), 256>>>(gt, out);
}